// round 9
// baseline (speedup 1.0000x reference)
#include <cuda_runtime.h>

// Problem constants: x[B,C,H,W] f32, gamma/beta [N,C], out [B, N*C, H, W]
#define B_   32
#define C_   64
#define HW_  1024          // H*W
#define N_   16
#define HW4_ 256           // HW in float4 units
#define NPLANES_ (B_ * C_) // 2048
#define GRP_  4            // batch groups in reduce
#define BPG_  (B_ / GRP_)  // 8 batches per group
#define INV_CNT (1.0f / (float)(B_ * HW_))  // 1/32768

// Scratch (static device globals; no allocation). Layout: [g*C + c]
__device__ float g_psum[GRP_ * C_];
__device__ float g_psq [GRP_ * C_];

// ---------------------------------------------------------------------------
// Kernel 1: partial sums. 256 blocks = (g in 0..3) x (c in 0..63).
// Each block covers 8 full (b,c) planes of one channel: 256 threads x
// 8 independent float4 loads (MLP=8) -> latency hidden, DRAM-bound.
// ---------------------------------------------------------------------------
__global__ __launch_bounds__(256) void reduce_kernel(const float4* __restrict__ x4) {
    const int c = blockIdx.x & (C_ - 1);
    const int g = blockIdx.x >> 6;           // 0..3
    const int t = threadIdx.x;               // 0..255 -> one float4 per plane

    float s = 0.f, q = 0.f;
    #pragma unroll
    for (int j = 0; j < BPG_; j++) {
        const int b = g * BPG_ + j;
        const float4 v = __ldg(&x4[(b * C_ + c) * HW4_ + t]);  // coalesced 4KB/plane
        s += v.x + v.y + v.z + v.w;
        q += v.x*v.x + v.y*v.y + v.z*v.z + v.w*v.w;
    }

    // block reduction: 8 warps
    #pragma unroll
    for (int o = 16; o > 0; o >>= 1) {
        s += __shfl_down_sync(0xFFFFFFFFu, s, o);
        q += __shfl_down_sync(0xFFFFFFFFu, q, o);
    }
    __shared__ float ss[8], qq[8];
    const int w = t >> 5;
    if ((t & 31) == 0) { ss[w] = s; qq[w] = q; }
    __syncthreads();
    if (t == 0) {
        float S = 0.f, Q = 0.f;
        #pragma unroll
        for (int i = 0; i < 8; i++) { S += ss[i]; Q += qq[i]; }
        g_psum[blockIdx.x] = S;   // blockIdx.x == g*C + c
        g_psq [blockIdx.x] = Q;
    }
}

// ---------------------------------------------------------------------------
// Kernel 2: apply with inline finalize. One block per (b,c) plane.
// Warp 0 folds the 4 partials -> mean/inv -> per-branch (sg, sb) in smem.
// Each thread: 1 float4 x load (L2 hit), 16 FMA'd float4 WRITE-BACK stores
// (output ~= L2 capacity; same addresses every replay -> dirty lines are
// overwritten in place, steady-state DRAM writes collapse, LTS-bound).
// ---------------------------------------------------------------------------
__global__ __launch_bounds__(256) void apply_kernel(const float4* __restrict__ x4,
                                                    const float* __restrict__ gamma,
                                                    const float* __restrict__ beta,
                                                    float4* __restrict__ out4) {
    __shared__ float sg[N_], sb[N_];

    const int bc = blockIdx.x;           // b*C + c
    const int c  = bc & (C_ - 1);
    const int b  = bc >> 6;
    const int t  = threadIdx.x;          // 0..255

    // issue the x load early; independent of the finalize work below
    const float4 v = __ldg(&x4[bc * HW4_ + t]);

    if (t < 32) {
        const int g = t & 3;             // lanes replicate groups 0..3
        float s = g_psum[g * C_ + c];
        float q = g_psq [g * C_ + c];
        s += __shfl_xor_sync(0xFFFFFFFFu, s, 1);
        s += __shfl_xor_sync(0xFFFFFFFFu, s, 2);
        q += __shfl_xor_sync(0xFFFFFFFFu, q, 1);
        q += __shfl_xor_sync(0xFFFFFFFFu, q, 2);
        const float mean = s * INV_CNT;
        const float var  = fmaf(-mean, mean, q * INV_CNT);  // biased var
        const float inv  = rsqrtf(var + 1e-5f);
        if (t < N_) {
            const float ga = gamma[t * C_ + c];
            const float be = beta [t * C_ + c];
            const float sgv = ga * inv;
            sg[t] = sgv;
            sb[t] = fmaf(-sgv, mean, be);
        }
    }
    __syncthreads();

    // out linear (float4 units): (b*(N*C) + n*C + c) * HW4 + t
    const int base = (b * (N_ * C_) + c) * HW4_ + t;

    #pragma unroll
    for (int n = 0; n < N_; n++) {
        const float s  = sg[n];
        const float tt = sb[n];
        float4 o;
        o.x = fmaf(s, v.x, tt);
        o.y = fmaf(s, v.y, tt);
        o.z = fmaf(s, v.z, tt);
        o.w = fmaf(s, v.w, tt);
        out4[base + n * (C_ * HW4_)] = o;   // write-back store (L2-resident output)
    }
}

// ---------------------------------------------------------------------------
extern "C" void kernel_launch(void* const* d_in, const int* in_sizes, int n_in,
                              void* d_out, int out_size) {
    const float4* x4    = (const float4*)d_in[0];  // x [32,64,32,32]
    const float*  gamma = (const float*) d_in[1];  // [16,64]
    const float*  beta  = (const float*) d_in[2];  // [16,64]
    float4*       out4  = (float4*)d_out;          // [32,1024,32,32]

    reduce_kernel<<<GRP_ * C_, 256>>>(x4);
    apply_kernel <<<NPLANES_, 256>>>(x4, gamma, beta, out4);
}